// round 16
// baseline (speedup 1.0000x reference)
#include <cuda_runtime.h>
#include <cuda_pipeline.h>
#include <math.h>

// ---------------- problem dims ----------------
#define B     256
#define L0    2048
#define L1    1022   // after conv1(k3)+pool(k3,s2)
#define L2    339    // after conv2(k5)+pool(k3,s3)
#define L2P   340    // padded row stride of g_h2 (even -> 8B-aligned rows)
#define L3    168    // after conv3(k3)+pool(k3,s2)
#define FCIN  10752  // 64*168

// ---------------- scratch (device globals; allocation-free rule) ----------------
__device__ float g_h1[B * 128 * L1];   // 134 MB
__device__ float g_h2[B * 64 * L2P];   // 22.3 MB (pad col never written/read)
__device__ float g_h3[B * FCIN];       // 11 MB
__device__ float g_theta[B * 5];
// BN-folded, oc-fastest transposed weights (filled by k_prep each launch)
__device__ float g_w2t[128 * 5 * 64];  // [(ic*5+k)*64 + oc]
__device__ float g_sh2[64];
__device__ float g_w3t[64 * 3 * 64];   // [(ic*3+k)*64 + oc]
__device__ float g_sh3[64];

// =====================================================================
// Kernel 0: fold BN into conv2/conv3 weights and transpose oc-fastest
// =====================================================================
__global__ void __launch_bounds__(256) k_prep(
    const float* __restrict__ w2, const float* __restrict__ cb2,
    const float* __restrict__ g2, const float* __restrict__ bt2,
    const float* __restrict__ mn2, const float* __restrict__ vr2,
    const float* __restrict__ w3, const float* __restrict__ cb3,
    const float* __restrict__ g3, const float* __restrict__ bt3,
    const float* __restrict__ mn3, const float* __restrict__ vr3)
{
    const int tid = blockIdx.x * 256 + threadIdx.x;
    const int nthr = gridDim.x * 256;
    for (int i = tid; i < 64 * 640; i += nthr) {
        int oc = i & 63, rk = i >> 6;
        float s = g2[oc] * rsqrtf(vr2[oc] + 1e-5f);
        g_w2t[i] = w2[oc * 640 + rk] * s;
    }
    for (int i = tid; i < 64 * 192; i += nthr) {
        int oc = i & 63, rk = i >> 6;
        float s = g3[oc] * rsqrtf(vr3[oc] + 1e-5f);
        g_w3t[i] = w3[oc * 192 + rk] * s;
    }
    if (tid < 64) {
        float s2 = g2[tid] * rsqrtf(vr2[tid] + 1e-5f);
        g_sh2[tid] = (cb2[tid] - mn2[tid]) * s2 + bt2[tid];
        float s3 = g3[tid] * rsqrtf(vr3[tid] + 1e-5f);
        g_sh3[tid] = (cb3[tid] - mn3[tid]) * s3 + bt3[tid];
    }
}

// =====================================================================
// Kernel 1: conv1(128,3,3) + BN + maxpool(k3,s2) + relu
// Sliding-window register cache; peeled loop (31 refill iters + epilogue).
// =====================================================================
__global__ void __launch_bounds__(256) k_conv1(
    const float* __restrict__ x, const float* __restrict__ w,
    const float* __restrict__ cb, const float* __restrict__ g,
    const float* __restrict__ bt, const float* __restrict__ mn,
    const float* __restrict__ vr)
{
    __shared__ float xs[3 * 132];
    __shared__ float out_s[128 * 65];

    const int b  = blockIdx.y;
    const int p0 = blockIdx.x * 64;
    const int tid = threadIdx.x;

    {   // staging with incremental (c, off) indexing
        int c = tid / 132, off = tid % 132;
        for (int idx = tid; idx < 3 * 132; idx += 256) {
            int gp = 2 * p0 + off;
            xs[idx] = (gp < L0) ? x[(b * 3 + c) * L0 + gp] : 0.f;
            off += 256;
            while (off >= 132) { off -= 132; ++c; }
        }
    }
    __syncthreads();

    const int oc = tid & 127;
    const int half = tid >> 7;

    const float scale = g[oc] * rsqrtf(vr[oc] + 1e-5f);
    const float shift = (cb[oc] - mn[oc]) * scale + bt[oc];
    float wr[9];
#pragma unroll
    for (int j = 0; j < 9; ++j) wr[j] = w[oc * 9 + j] * scale;

    const int ps = half * 32;
    int lq = 2 * ps;

    // window v[c][m] = xs[c][lq+m], m=0..4
    float v[3][5];
#pragma unroll
    for (int c = 0; c < 3; ++c)
#pragma unroll
        for (int m = 0; m < 5; ++m) v[c][m] = xs[c * 132 + lq + m];

    float c0 = 0.f;
#pragma unroll
    for (int c = 0; c < 3; ++c)
#pragma unroll
        for (int k = 0; k < 3; ++k) c0 += wr[c * 3 + k] * v[c][k];

    // 31 iterations with refill (bounds: max read lq+6 = 2ps+66 <= 130 < 132)
    for (int pl = ps; pl < ps + 31; ++pl) {
        float c1 = 0.f, c2 = 0.f;
#pragma unroll
        for (int c = 0; c < 3; ++c)
#pragma unroll
            for (int k = 0; k < 3; ++k) {
                c1 += wr[c * 3 + k] * v[c][k + 1];
                c2 += wr[c * 3 + k] * v[c][k + 2];
            }
        float y = fmaxf(fmaxf(c0, c1), c2) + shift;
        out_s[oc * 65 + pl] = fmaxf(y, 0.f);
        c0 = c2;
#pragma unroll
        for (int c = 0; c < 3; ++c) {
            v[c][0] = v[c][2]; v[c][1] = v[c][3]; v[c][2] = v[c][4];
            v[c][3] = xs[c * 132 + lq + 5];
            v[c][4] = xs[c * 132 + lq + 6];
        }
        lq += 2;
    }
    {   // epilogue: final pooled position, no refill
        float c1 = 0.f, c2 = 0.f;
#pragma unroll
        for (int c = 0; c < 3; ++c)
#pragma unroll
            for (int k = 0; k < 3; ++k) {
                c1 += wr[c * 3 + k] * v[c][k + 1];
                c2 += wr[c * 3 + k] * v[c][k + 2];
            }
        float y = fmaxf(fmaxf(c0, c1), c2) + shift;
        out_s[oc * 65 + (ps + 31)] = fmaxf(y, 0.f);
    }
    __syncthreads();

    for (int idx = tid; idx < 128 * 64; idx += 256) {
        int o = idx >> 6, pl = idx & 63;
        int p = p0 + pl;
        if (p < L1) g_h1[(b * 128 + o) * L1 + p] = out_s[o * 65 + pl];
    }
}

// =====================================================================
// conv2 tile body (templated); cp.async double-buffered, 16 chunks of 8 ic.
// Weights pre-transposed oc-fastest; inner loop: 2x LDS.128 per (ic,k).
// =====================================================================
template<int NG>
__device__ __forceinline__ void conv2_tile(
    int b, int p0, float* w_s0, float* w_s1, float* in_s0, float* in_s1)
{
    const int SPAN  = 96 * NG + 4;   // conv-input span (even)
    const int PAIRS = SPAN / 2;
    float* w_sb[2]  = { w_s0, w_s1 };
    float* in_sb[2] = { in_s0, in_s1 };

    const int tid = threadIdx.x;
    const int ocg = tid >> 5, pg = tid & 31;
    const int i_r0 = tid / PAIRS, i_q0 = tid % PAIRS;
    const float* const srcb = &g_h1[(size_t)(b * 128) * L1];

    auto stage = [&](int s, int c) {
        const float4* wsrc = (const float4*)(g_w2t + c * (8 * 5 * 64));
        float4* wdst = (float4*)w_sb[s];
#pragma unroll
        for (int it = 0; it < 3; ++it) {
            int idx = tid + 256 * it;
            if (idx < 640)
                __pipeline_memcpy_async(&wdst[idx], &wsrc[idx], 16);
        }
        int r = i_r0, q = i_q0;
        const float* src = srcb + (size_t)(c * 8) * L1;
        for (int idx = tid; idx < 8 * PAIRS; idx += 256) {
            int gp = 3 * p0 + 2 * q;
            float* d = &in_sb[s][r * SPAN + 2 * q];
            if (gp + 1 < L1) {          // L1 even: pairs are all-in or all-out
                __pipeline_memcpy_async(d, src + (size_t)r * L1 + gp, 8);
            } else {
                d[0] = 0.f; d[1] = 0.f;
            }
            q += 256;
            while (q >= PAIRS) { q -= PAIRS; ++r; }
        }
    };

    float acc[8][3 * NG];
#pragma unroll
    for (int o = 0; o < 8; ++o)
#pragma unroll
        for (int j = 0; j < 3 * NG; ++j) acc[o][j] = 0.f;

    stage(0, 0);
    __pipeline_commit();
    __pipeline_wait_prior(0);
    __syncthreads();

    for (int c = 0; c < 16; ++c) {
        const int cur = c & 1;
        if (c + 1 < 16) { stage(1 - cur, c + 1); __pipeline_commit(); }

#pragma unroll 2
        for (int icl = 0; icl < 8; ++icl) {
            const int base = icl * SPAN + 3 * pg;
            float rv[NG][7];
#pragma unroll
            for (int gI = 0; gI < NG; ++gI)
#pragma unroll
                for (int m = 0; m < 7; ++m)
                    rv[gI][m] = in_sb[cur][base + 96 * gI + m];
#pragma unroll
            for (int k = 0; k < 5; ++k) {
                float w8[8];
                const int wbase = (icl * 5 + k) * 64 + ocg * 8;
                *(float4*)&w8[0] = *(const float4*)&w_sb[cur][wbase];
                *(float4*)&w8[4] = *(const float4*)&w_sb[cur][wbase + 4];
#pragma unroll
                for (int o = 0; o < 8; ++o) {
                    const float wv = w8[o];
#pragma unroll
                    for (int gI = 0; gI < NG; ++gI) {
                        acc[o][3 * gI + 0] += wv * rv[gI][k];
                        acc[o][3 * gI + 1] += wv * rv[gI][k + 1];
                        acc[o][3 * gI + 2] += wv * rv[gI][k + 2];
                    }
                }
            }
        }

        if (c + 1 < 16) __pipeline_wait_prior(0);
        __syncthreads();
    }

#pragma unroll
    for (int o = 0; o < 8; ++o) {
        int oc = ocg * 8 + o;
        float shift = g_sh2[oc];
#pragma unroll
        for (int gI = 0; gI < NG; ++gI) {
            int p = p0 + pg + 32 * gI;
            if (p < L2) {
                float y = fmaxf(fmaxf(acc[o][3 * gI], acc[o][3 * gI + 1]),
                                acc[o][3 * gI + 2]) + shift;
                g_h2[(size_t)(b * 64 + oc) * L2P + p] = fmaxf(y, 0.f);
            }
        }
    }
}

// Kernel 2 (merged): grid (4, B); x<3 -> NG=3 tile, x==3 -> NG=2 tail tile.
__global__ void __launch_bounds__(256) k_conv2m()
{
    // sized for the larger (NG=3) instantiation; NG=2 reuses a prefix
    __shared__ __align__(16) float w_s[2][8 * 5 * 64];    // 2 x 10 KB
    __shared__ __align__(16) float in_s[2][8 * 292];      // 2 x 9.1 KB

    const int b = blockIdx.y;
    if (blockIdx.x < 3)
        conv2_tile<3>(b, blockIdx.x * 96, w_s[0], w_s[1], in_s[0], in_s[1]);
    else
        conv2_tile<2>(b, 288, w_s[0], w_s[1], in_s[0], in_s[1]);
}

// =====================================================================
// Kernel 3: conv3(64,64,3) + BN + maxpool(k3,s2) + relu, writes flattened h
// grid (B, 3); cp.async double-buffered, 8 chunks of 8 ic.
// =====================================================================
__global__ void __launch_bounds__(256) k_conv3()
{
    __shared__ __align__(16) float w_s[2][8 * 3 * 64];   // 2 x 6 KB
    __shared__ __align__(16) float in_s[2][8 * 132];     // 2 x 4.2 KB

    const int b  = blockIdx.x;
    const int pb = blockIdx.y * 64;
    const int tid = threadIdx.x;
    const int ocg = tid >> 5, pg = tid & 31;

    const int i_r0 = tid / 66, i_q0 = tid % 66;          // 66 pairs per 132-row
    const float* const srcb = &g_h2[(size_t)(b * 64) * L2P];

    auto stage = [&](int s, int c) {
        const float4* wsrc = (const float4*)(g_w3t + c * (8 * 3 * 64));
        float4* wdst = (float4*)w_s[s];
#pragma unroll
        for (int it = 0; it < 2; ++it) {
            int idx = tid + 256 * it;
            if (idx < 384)
                __pipeline_memcpy_async(&wdst[idx], &wsrc[idx], 16);
        }
        int r = i_r0, q = i_q0;
        const float* src = srcb + (size_t)(c * 8) * L2P;
        for (int idx = tid; idx < 8 * 66; idx += 256) {
            int gp = 2 * pb + 2 * q;
            float* d = &in_s[s][r * 132 + 2 * q];
            if (gp + 1 < L2) {                       // full pair valid
                __pipeline_memcpy_async(d, src + (size_t)r * L2P + gp, 8);
            } else if (gp < L2) {                    // gp==338: single element
                __pipeline_memcpy_async(d, src + (size_t)r * L2P + gp, 4);
                d[1] = 0.f;
            } else {
                d[0] = 0.f; d[1] = 0.f;
            }
            q += 256;
            while (q >= 66) { q -= 66; ++r; }
        }
    };

    float acc[8][6];
#pragma unroll
    for (int o = 0; o < 8; ++o)
#pragma unroll
        for (int j = 0; j < 6; ++j) acc[o][j] = 0.f;

    stage(0, 0);
    __pipeline_commit();
    __pipeline_wait_prior(0);
    __syncthreads();

    for (int c = 0; c < 8; ++c) {
        const int cur = c & 1;
        if (c + 1 < 8) { stage(1 - cur, c + 1); __pipeline_commit(); }

#pragma unroll 4
        for (int icl = 0; icl < 8; ++icl) {
            const int base = icl * 132 + 2 * pg;
            float iv[5], jv[5];
#pragma unroll
            for (int m = 0; m < 5; ++m) {
                iv[m] = in_s[cur][base + m];
                jv[m] = in_s[cur][base + 64 + m];
            }
#pragma unroll
            for (int k = 0; k < 3; ++k) {
                float w8[8];
                const int wbase = (icl * 3 + k) * 64 + ocg * 8;
                *(float4*)&w8[0] = *(const float4*)&w_s[cur][wbase];
                *(float4*)&w8[4] = *(const float4*)&w_s[cur][wbase + 4];
                const float i0 = iv[k], i1 = iv[k + 1], i2 = iv[k + 2];
                const float j0 = jv[k], j1 = jv[k + 1], j2 = jv[k + 2];
#pragma unroll
                for (int o = 0; o < 8; ++o) {
                    const float wv = w8[o];
                    acc[o][0] += wv * i0; acc[o][1] += wv * i1; acc[o][2] += wv * i2;
                    acc[o][3] += wv * j0; acc[o][4] += wv * j1; acc[o][5] += wv * j2;
                }
            }
        }

        if (c + 1 < 8) __pipeline_wait_prior(0);
        __syncthreads();
    }

    const int p1 = pb + pg, p2 = p1 + 32;
#pragma unroll
    for (int o = 0; o < 8; ++o) {
        int oc = ocg * 8 + o;
        float shift = g_sh3[oc];
        if (p1 < L3) {
            float y = fmaxf(fmaxf(acc[o][0], acc[o][1]), acc[o][2]) + shift;
            g_h3[(size_t)b * FCIN + oc * L3 + p1] = fmaxf(y, 0.f);
        }
        if (p2 < L3) {
            float y = fmaxf(fmaxf(acc[o][3], acc[o][4]), acc[o][5]) + shift;
            g_h3[(size_t)b * FCIN + oc * L3 + p2] = fmaxf(y, 0.f);
        }
    }
}

// =====================================================================
// Kernel 4: fc1(48) -> fc2(32) -> fc3(16) -> fc4(5) -> tanh
// 4 batches/block, 64 blocks
// =====================================================================
__global__ void __launch_bounds__(256) k_fc(
    const float* __restrict__ w1, const float* __restrict__ b1,
    const float* __restrict__ w2, const float* __restrict__ b2,
    const float* __restrict__ w3, const float* __restrict__ b3,
    const float* __restrict__ w4, const float* __restrict__ b4)
{
    __shared__ float hs[4 * 1344];
    __shared__ float s1[4][48];
    __shared__ float s2[4][32];
    __shared__ float s3[4][16];

    const int b0 = blockIdx.x * 4;
    const int tid = threadIdx.x, wid = tid >> 5, lane = tid & 31;

    const int h_b0 = tid / 1344, h_k0 = tid % 1344;   // incremental staging

    float acc[6][4];
#pragma unroll
    for (int a = 0; a < 6; ++a)
#pragma unroll
        for (int bi = 0; bi < 4; ++bi) acc[a][bi] = 0.f;

    for (int c0 = 0; c0 < FCIN; c0 += 1344) {
        __syncthreads();
        {
            int bi = h_b0, kk = h_k0;
            for (int idx = tid; idx < 4 * 1344; idx += 256) {
                hs[idx] = g_h3[(size_t)(b0 + bi) * FCIN + c0 + kk];
                kk += 256;
                while (kk >= 1344) { kk -= 1344; ++bi; }
            }
        }
        __syncthreads();
        for (int o6 = 0; o6 < 6; ++o6) {
            int o = wid * 6 + o6;
            for (int kk = lane; kk < 1344; kk += 32) {
                float wv = w1[(size_t)o * FCIN + c0 + kk];
#pragma unroll
                for (int bi = 0; bi < 4; ++bi) acc[o6][bi] += wv * hs[bi * 1344 + kk];
            }
        }
    }

    for (int o6 = 0; o6 < 6; ++o6)
        for (int bi = 0; bi < 4; ++bi) {
            float v = acc[o6][bi];
            for (int s = 16; s; s >>= 1) v += __shfl_xor_sync(0xffffffffu, v, s);
            if (lane == 0) {
                int o = wid * 6 + o6;
                s1[bi][o] = fmaxf(v + b1[o], 0.f);
            }
        }
    __syncthreads();

    if (tid < 128) {
        int bi = tid >> 5, o = tid & 31;
        float v = b2[o];
        for (int j = 0; j < 48; ++j) v += s1[bi][j] * w2[o * 48 + j];
        s2[bi][o] = fmaxf(v, 0.f);
    }
    __syncthreads();
    if (tid < 64) {
        int bi = tid >> 4, o = tid & 15;
        float v = b3[o];
        for (int j = 0; j < 32; ++j) v += s2[bi][j] * w3[o * 32 + j];
        s3[bi][o] = fmaxf(v, 0.f);
    }
    __syncthreads();
    if (tid < 20) {
        int bi = tid / 5, o = tid % 5;
        float v = b4[o];
        for (int j = 0; j < 16; ++j) v += s3[bi][j] * w4[o * 16 + j];
        g_theta[(b0 + bi) * 5 + o] = tanhf(v);
    }
}

// =====================================================================
// Kernel 5: CPAB integration (double, exact cell-crossing, early-exit)
//           + linear interpolation of the original signal
// =====================================================================
__global__ void __launch_bounds__(256) k_warp(
    const float* __restrict__ x, const float* __restrict__ basis,
    float* __restrict__ out)
{
    __shared__ double As[12];
    const int b = blockIdx.y;
    const int i = blockIdx.x * 256 + threadIdx.x;

    if (threadIdx.x < 12) {
        double s = 0.0;
        for (int d = 0; d < 5; ++d)
            s += (double)g_theta[b * 5 + d] * (double)basis[threadIdx.x * 5 + d];
        As[threadIdx.x] = s;
    }
    __syncthreads();

    float xf = (i == 2047) ? 1.0f : (float)i * (1.0f / 2047.0f);
    double xx = (double)xf;
    double t = 1.0;

    for (int it = 0; it < 7; ++it) {
        if (t == 0.0) break;
        int c = (int)floor(xx * 6.0);
        c = max(0, min(c, 5));
        double a  = As[2 * c];
        double bb = As[2 * c + 1];
        double v = a * xx + bb;
        double xb = (v >= 0.0) ? (double)(c + 1) / 6.0 : (double)c / 6.0;
        bool big_a = fabs(a) > 1e-8;
        double a_s = big_a ? a : 1.0;
        double z  = xx + bb / a_s;
        double zb = xb + bb / a_s;
        double zden = (fabs(z) > 1e-12) ? z : 1e-12;
        double ratio = zb / zden;
        double t_exp = log(fmax(ratio, 1e-12)) / a_s;
        double v_s = (fabs(v) > 1e-12) ? v : 1.0;
        double t_lin = (xb - xx) / v_s;
        double thit = big_a ? t_exp : t_lin;
        bool valid = (fabs(v) > 1e-12) && (thit > 0.0) && ((big_a ? ratio : 1.0) > 0.0);
        if (!valid) thit = 1e300;
        double tau = fmin(t, thit);
        double x_new = big_a ? (z * exp(a * tau) - (z - xx)) : (xx + bb * tau);
        bool hit = (thit <= t);
        double nudge = (v >= 0.0) ? 1e-6 : -1e-6;
        xx = hit ? (xb + nudge) : x_new;
        xx = fmin(fmax(xx, 0.0), 1.0);
        t = fmax(t - tau, 0.0);
    }

    float xt = (float)xx;
    xt = fminf(fmaxf(xt, 0.f), 1.f);
    float p = xt * 2047.0f;
    int x0 = (int)floorf(p);
    x0 = max(0, min(x0, 2046));
    float wgt = p - (float)x0;
    const float* xb_ = x + (size_t)b * 3 * L0;
#pragma unroll
    for (int c = 0; c < 3; ++c) {
        float d0 = xb_[c * L0 + x0];
        float d1 = xb_[c * L0 + x0 + 1];
        out[((size_t)b * 3 + c) * L0 + i] = d0 * (1.f - wgt) + d1 * wgt;
    }
}

// =====================================================================
extern "C" void kernel_launch(void* const* d_in, const int* in_sizes, int n_in,
                              void* d_out, int out_size)
{
    const float* x  = (const float*)d_in[0];

    k_prep<<<40, 256>>>(
        (const float*)d_in[7],  (const float*)d_in[8],  (const float*)d_in[9],
        (const float*)d_in[10], (const float*)d_in[11], (const float*)d_in[12],
        (const float*)d_in[13], (const float*)d_in[14], (const float*)d_in[15],
        (const float*)d_in[16], (const float*)d_in[17], (const float*)d_in[18]);

    k_conv1<<<dim3(16, B), 256>>>(x,
        (const float*)d_in[1], (const float*)d_in[2], (const float*)d_in[3],
        (const float*)d_in[4], (const float*)d_in[5], (const float*)d_in[6]);

    k_conv2m<<<dim3(4, B), 256>>>();

    k_conv3<<<dim3(B, 3), 256>>>();

    k_fc<<<64, 256>>>(
        (const float*)d_in[19], (const float*)d_in[20], (const float*)d_in[21],
        (const float*)d_in[22], (const float*)d_in[23], (const float*)d_in[24],
        (const float*)d_in[25], (const float*)d_in[26]);

    k_warp<<<dim3(8, B), 256>>>(x, (const float*)d_in[27], (float*)d_out);
}

// round 17
// speedup vs baseline: 1.0236x; 1.0236x over previous
#include <cuda_runtime.h>
#include <cuda_pipeline.h>
#include <math.h>

// ---------------- problem dims ----------------
#define B     256
#define L0    2048
#define L1    1022   // after conv1(k3)+pool(k3,s2)
#define L2    339    // after conv2(k5)+pool(k3,s3)
#define L2P   340    // padded row stride of g_h2 (even -> 8B-aligned rows)
#define L3    168    // after conv3(k3)+pool(k3,s2)
#define FCIN  10752  // 64*168

// ---------------- scratch (device globals; allocation-free rule) ----------------
__device__ float g_h1[B * 128 * L1];   // 134 MB
__device__ float g_h2[B * 64 * L2P];   // 22.3 MB (pad col never written/read)
__device__ float g_h3[B * FCIN];       // 11 MB
__device__ float g_theta[B * 5];
// BN-folded, oc-fastest transposed weights (filled by k_prep each launch)
__device__ float g_w2t[128 * 5 * 64];  // [(ic*5+k)*64 + oc]
__device__ float g_sh2[64];
__device__ float g_w3t[64 * 3 * 64];   // [(ic*3+k)*64 + oc]
__device__ float g_sh3[64];

// =====================================================================
// Kernel 0: fold BN into conv2/conv3 weights and transpose oc-fastest
// =====================================================================
__global__ void __launch_bounds__(256) k_prep(
    const float* __restrict__ w2, const float* __restrict__ cb2,
    const float* __restrict__ g2, const float* __restrict__ bt2,
    const float* __restrict__ mn2, const float* __restrict__ vr2,
    const float* __restrict__ w3, const float* __restrict__ cb3,
    const float* __restrict__ g3, const float* __restrict__ bt3,
    const float* __restrict__ mn3, const float* __restrict__ vr3)
{
    const int tid = blockIdx.x * 256 + threadIdx.x;
    const int nthr = gridDim.x * 256;
    for (int i = tid; i < 64 * 640; i += nthr) {
        int oc = i & 63, rk = i >> 6;
        float s = g2[oc] * rsqrtf(vr2[oc] + 1e-5f);
        g_w2t[i] = w2[oc * 640 + rk] * s;
    }
    for (int i = tid; i < 64 * 192; i += nthr) {
        int oc = i & 63, rk = i >> 6;
        float s = g3[oc] * rsqrtf(vr3[oc] + 1e-5f);
        g_w3t[i] = w3[oc * 192 + rk] * s;
    }
    if (tid < 64) {
        float s2 = g2[tid] * rsqrtf(vr2[tid] + 1e-5f);
        g_sh2[tid] = (cb2[tid] - mn2[tid]) * s2 + bt2[tid];
        float s3 = g3[tid] * rsqrtf(vr3[tid] + 1e-5f);
        g_sh3[tid] = (cb3[tid] - mn3[tid]) * s3 + bt3[tid];
    }
}

// =====================================================================
// Kernel 1: conv1(128,3,3) + BN + maxpool(k3,s2) + relu
// Sliding-window register cache; peeled loop (31 refill iters + epilogue).
// =====================================================================
__global__ void __launch_bounds__(256, 2) k_conv1(
    const float* __restrict__ x, const float* __restrict__ w,
    const float* __restrict__ cb, const float* __restrict__ g,
    const float* __restrict__ bt, const float* __restrict__ mn,
    const float* __restrict__ vr)
{
    __shared__ float xs[3 * 132];
    __shared__ float out_s[128 * 65];

    const int b  = blockIdx.y;
    const int p0 = blockIdx.x * 64;
    const int tid = threadIdx.x;

    {   // staging with incremental (c, off) indexing
        int c = tid / 132, off = tid % 132;
        for (int idx = tid; idx < 3 * 132; idx += 256) {
            int gp = 2 * p0 + off;
            xs[idx] = (gp < L0) ? x[(b * 3 + c) * L0 + gp] : 0.f;
            off += 256;
            while (off >= 132) { off -= 132; ++c; }
        }
    }
    __syncthreads();

    const int oc = tid & 127;
    const int half = tid >> 7;

    const float scale = g[oc] * rsqrtf(vr[oc] + 1e-5f);
    const float shift = (cb[oc] - mn[oc]) * scale + bt[oc];
    float wr[9];
#pragma unroll
    for (int j = 0; j < 9; ++j) wr[j] = w[oc * 9 + j] * scale;

    const int ps = half * 32;
    int lq = 2 * ps;

    // window v[c][m] = xs[c][lq+m], m=0..4
    float v[3][5];
#pragma unroll
    for (int c = 0; c < 3; ++c)
#pragma unroll
        for (int m = 0; m < 5; ++m) v[c][m] = xs[c * 132 + lq + m];

    float c0 = 0.f;
#pragma unroll
    for (int c = 0; c < 3; ++c)
#pragma unroll
        for (int k = 0; k < 3; ++k) c0 += wr[c * 3 + k] * v[c][k];

    // 31 iterations with refill (bounds: max read lq+6 = 2ps+66 <= 130 < 132)
    for (int pl = ps; pl < ps + 31; ++pl) {
        float c1 = 0.f, c2 = 0.f;
#pragma unroll
        for (int c = 0; c < 3; ++c)
#pragma unroll
            for (int k = 0; k < 3; ++k) {
                c1 += wr[c * 3 + k] * v[c][k + 1];
                c2 += wr[c * 3 + k] * v[c][k + 2];
            }
        float y = fmaxf(fmaxf(c0, c1), c2) + shift;
        out_s[oc * 65 + pl] = fmaxf(y, 0.f);
        c0 = c2;
#pragma unroll
        for (int c = 0; c < 3; ++c) {
            v[c][0] = v[c][2]; v[c][1] = v[c][3]; v[c][2] = v[c][4];
            v[c][3] = xs[c * 132 + lq + 5];
            v[c][4] = xs[c * 132 + lq + 6];
        }
        lq += 2;
    }
    {   // epilogue: final pooled position, no refill
        float c1 = 0.f, c2 = 0.f;
#pragma unroll
        for (int c = 0; c < 3; ++c)
#pragma unroll
            for (int k = 0; k < 3; ++k) {
                c1 += wr[c * 3 + k] * v[c][k + 1];
                c2 += wr[c * 3 + k] * v[c][k + 2];
            }
        float y = fmaxf(fmaxf(c0, c1), c2) + shift;
        out_s[oc * 65 + (ps + 31)] = fmaxf(y, 0.f);
    }
    __syncthreads();

    for (int idx = tid; idx < 128 * 64; idx += 256) {
        int o = idx >> 6, pl = idx & 63;
        int p = p0 + pl;
        if (p < L1) g_h1[(b * 128 + o) * L1 + p] = out_s[o * 65 + pl];
    }
}

// =====================================================================
// conv2 tile body (templated); cp.async double-buffered, 16 chunks of 8 ic.
// Weights pre-transposed oc-fastest; inner loop: 2x LDS.128 per (ic,k).
// =====================================================================
template<int NG>
__device__ __forceinline__ void conv2_tile(
    int b, int p0, float* w_s0, float* w_s1, float* in_s0, float* in_s1)
{
    const int SPAN  = 96 * NG + 4;   // conv-input span (even)
    const int PAIRS = SPAN / 2;
    float* w_sb[2]  = { w_s0, w_s1 };
    float* in_sb[2] = { in_s0, in_s1 };

    const int tid = threadIdx.x;
    const int ocg = tid >> 5, pg = tid & 31;
    const int i_r0 = tid / PAIRS, i_q0 = tid % PAIRS;
    const float* const srcb = &g_h1[(size_t)(b * 128) * L1];

    auto stage = [&](int s, int c) {
        const float4* wsrc = (const float4*)(g_w2t + c * (8 * 5 * 64));
        float4* wdst = (float4*)w_sb[s];
#pragma unroll
        for (int it = 0; it < 3; ++it) {
            int idx = tid + 256 * it;
            if (idx < 640)
                __pipeline_memcpy_async(&wdst[idx], &wsrc[idx], 16);
        }
        int r = i_r0, q = i_q0;
        const float* src = srcb + (size_t)(c * 8) * L1;
        for (int idx = tid; idx < 8 * PAIRS; idx += 256) {
            int gp = 3 * p0 + 2 * q;
            float* d = &in_sb[s][r * SPAN + 2 * q];
            if (gp + 1 < L1) {          // L1 even: pairs are all-in or all-out
                __pipeline_memcpy_async(d, src + (size_t)r * L1 + gp, 8);
            } else {
                d[0] = 0.f; d[1] = 0.f;
            }
            q += 256;
            while (q >= PAIRS) { q -= PAIRS; ++r; }
        }
    };

    float acc[8][3 * NG];
#pragma unroll
    for (int o = 0; o < 8; ++o)
#pragma unroll
        for (int j = 0; j < 3 * NG; ++j) acc[o][j] = 0.f;

    stage(0, 0);
    __pipeline_commit();
    __pipeline_wait_prior(0);
    __syncthreads();

    for (int c = 0; c < 16; ++c) {
        const int cur = c & 1;
        if (c + 1 < 16) { stage(1 - cur, c + 1); __pipeline_commit(); }

#pragma unroll 2
        for (int icl = 0; icl < 8; ++icl) {
            const int base = icl * SPAN + 3 * pg;
            float rv[NG][7];
#pragma unroll
            for (int gI = 0; gI < NG; ++gI)
#pragma unroll
                for (int m = 0; m < 7; ++m)
                    rv[gI][m] = in_sb[cur][base + 96 * gI + m];
#pragma unroll
            for (int k = 0; k < 5; ++k) {
                float w8[8];
                const int wbase = (icl * 5 + k) * 64 + ocg * 8;
                *(float4*)&w8[0] = *(const float4*)&w_sb[cur][wbase];
                *(float4*)&w8[4] = *(const float4*)&w_sb[cur][wbase + 4];
#pragma unroll
                for (int o = 0; o < 8; ++o) {
                    const float wv = w8[o];
#pragma unroll
                    for (int gI = 0; gI < NG; ++gI) {
                        acc[o][3 * gI + 0] += wv * rv[gI][k];
                        acc[o][3 * gI + 1] += wv * rv[gI][k + 1];
                        acc[o][3 * gI + 2] += wv * rv[gI][k + 2];
                    }
                }
            }
        }

        if (c + 1 < 16) __pipeline_wait_prior(0);
        __syncthreads();
    }

#pragma unroll
    for (int o = 0; o < 8; ++o) {
        int oc = ocg * 8 + o;
        float shift = g_sh2[oc];
#pragma unroll
        for (int gI = 0; gI < NG; ++gI) {
            int p = p0 + pg + 32 * gI;
            if (p < L2) {
                float y = fmaxf(fmaxf(acc[o][3 * gI], acc[o][3 * gI + 1]),
                                acc[o][3 * gI + 2]) + shift;
                g_h2[(size_t)(b * 64 + oc) * L2P + p] = fmaxf(y, 0.f);
            }
        }
    }
}

// Kernel 2 (merged): grid (4, B); x<3 -> NG=3 tile, x==3 -> NG=2 tail tile.
// min 2 blocks/SM: caps regs at 128 so two CTAs co-reside and hide the
// per-chunk barrier/staging latency across CTAs.
__global__ void __launch_bounds__(256, 2) k_conv2m()
{
    // sized for the larger (NG=3) instantiation; NG=2 reuses a prefix
    __shared__ __align__(16) float w_s[2][8 * 5 * 64];    // 2 x 10 KB
    __shared__ __align__(16) float in_s[2][8 * 292];      // 2 x 9.1 KB

    const int b = blockIdx.y;
    if (blockIdx.x < 3)
        conv2_tile<3>(b, blockIdx.x * 96, w_s[0], w_s[1], in_s[0], in_s[1]);
    else
        conv2_tile<2>(b, 288, w_s[0], w_s[1], in_s[0], in_s[1]);
}

// =====================================================================
// Kernel 3: conv3(64,64,3) + BN + maxpool(k3,s2) + relu, writes flattened h
// grid (B, 3); cp.async double-buffered, 8 chunks of 8 ic.
// =====================================================================
__global__ void __launch_bounds__(256, 2) k_conv3()
{
    __shared__ __align__(16) float w_s[2][8 * 3 * 64];   // 2 x 6 KB
    __shared__ __align__(16) float in_s[2][8 * 132];     // 2 x 4.2 KB

    const int b  = blockIdx.x;
    const int pb = blockIdx.y * 64;
    const int tid = threadIdx.x;
    const int ocg = tid >> 5, pg = tid & 31;

    const int i_r0 = tid / 66, i_q0 = tid % 66;          // 66 pairs per 132-row
    const float* const srcb = &g_h2[(size_t)(b * 64) * L2P];

    auto stage = [&](int s, int c) {
        const float4* wsrc = (const float4*)(g_w3t + c * (8 * 3 * 64));
        float4* wdst = (float4*)w_s[s];
#pragma unroll
        for (int it = 0; it < 2; ++it) {
            int idx = tid + 256 * it;
            if (idx < 384)
                __pipeline_memcpy_async(&wdst[idx], &wsrc[idx], 16);
        }
        int r = i_r0, q = i_q0;
        const float* src = srcb + (size_t)(c * 8) * L2P;
        for (int idx = tid; idx < 8 * 66; idx += 256) {
            int gp = 2 * pb + 2 * q;
            float* d = &in_s[s][r * 132 + 2 * q];
            if (gp + 1 < L2) {                       // full pair valid
                __pipeline_memcpy_async(d, src + (size_t)r * L2P + gp, 8);
            } else if (gp < L2) {                    // gp==338: single element
                __pipeline_memcpy_async(d, src + (size_t)r * L2P + gp, 4);
                d[1] = 0.f;
            } else {
                d[0] = 0.f; d[1] = 0.f;
            }
            q += 256;
            while (q >= 66) { q -= 66; ++r; }
        }
    };

    float acc[8][6];
#pragma unroll
    for (int o = 0; o < 8; ++o)
#pragma unroll
        for (int j = 0; j < 6; ++j) acc[o][j] = 0.f;

    stage(0, 0);
    __pipeline_commit();
    __pipeline_wait_prior(0);
    __syncthreads();

    for (int c = 0; c < 8; ++c) {
        const int cur = c & 1;
        if (c + 1 < 8) { stage(1 - cur, c + 1); __pipeline_commit(); }

#pragma unroll 4
        for (int icl = 0; icl < 8; ++icl) {
            const int base = icl * 132 + 2 * pg;
            float iv[5], jv[5];
#pragma unroll
            for (int m = 0; m < 5; ++m) {
                iv[m] = in_s[cur][base + m];
                jv[m] = in_s[cur][base + 64 + m];
            }
#pragma unroll
            for (int k = 0; k < 3; ++k) {
                float w8[8];
                const int wbase = (icl * 3 + k) * 64 + ocg * 8;
                *(float4*)&w8[0] = *(const float4*)&w_s[cur][wbase];
                *(float4*)&w8[4] = *(const float4*)&w_s[cur][wbase + 4];
                const float i0 = iv[k], i1 = iv[k + 1], i2 = iv[k + 2];
                const float j0 = jv[k], j1 = jv[k + 1], j2 = jv[k + 2];
#pragma unroll
                for (int o = 0; o < 8; ++o) {
                    const float wv = w8[o];
                    acc[o][0] += wv * i0; acc[o][1] += wv * i1; acc[o][2] += wv * i2;
                    acc[o][3] += wv * j0; acc[o][4] += wv * j1; acc[o][5] += wv * j2;
                }
            }
        }

        if (c + 1 < 8) __pipeline_wait_prior(0);
        __syncthreads();
    }

    const int p1 = pb + pg, p2 = p1 + 32;
#pragma unroll
    for (int o = 0; o < 8; ++o) {
        int oc = ocg * 8 + o;
        float shift = g_sh3[oc];
        if (p1 < L3) {
            float y = fmaxf(fmaxf(acc[o][0], acc[o][1]), acc[o][2]) + shift;
            g_h3[(size_t)b * FCIN + oc * L3 + p1] = fmaxf(y, 0.f);
        }
        if (p2 < L3) {
            float y = fmaxf(fmaxf(acc[o][3], acc[o][4]), acc[o][5]) + shift;
            g_h3[(size_t)b * FCIN + oc * L3 + p2] = fmaxf(y, 0.f);
        }
    }
}

// =====================================================================
// Kernel 4: fc1(48) -> fc2(32) -> fc3(16) -> fc4(5) -> tanh
// 4 batches/block, 64 blocks
// =====================================================================
__global__ void __launch_bounds__(256) k_fc(
    const float* __restrict__ w1, const float* __restrict__ b1,
    const float* __restrict__ w2, const float* __restrict__ b2,
    const float* __restrict__ w3, const float* __restrict__ b3,
    const float* __restrict__ w4, const float* __restrict__ b4)
{
    __shared__ float hs[4 * 1344];
    __shared__ float s1[4][48];
    __shared__ float s2[4][32];
    __shared__ float s3[4][16];

    const int b0 = blockIdx.x * 4;
    const int tid = threadIdx.x, wid = tid >> 5, lane = tid & 31;

    const int h_b0 = tid / 1344, h_k0 = tid % 1344;   // incremental staging

    float acc[6][4];
#pragma unroll
    for (int a = 0; a < 6; ++a)
#pragma unroll
        for (int bi = 0; bi < 4; ++bi) acc[a][bi] = 0.f;

    for (int c0 = 0; c0 < FCIN; c0 += 1344) {
        __syncthreads();
        {
            int bi = h_b0, kk = h_k0;
            for (int idx = tid; idx < 4 * 1344; idx += 256) {
                hs[idx] = g_h3[(size_t)(b0 + bi) * FCIN + c0 + kk];
                kk += 256;
                while (kk >= 1344) { kk -= 1344; ++bi; }
            }
        }
        __syncthreads();
        for (int o6 = 0; o6 < 6; ++o6) {
            int o = wid * 6 + o6;
            for (int kk = lane; kk < 1344; kk += 32) {
                float wv = w1[(size_t)o * FCIN + c0 + kk];
#pragma unroll
                for (int bi = 0; bi < 4; ++bi) acc[o6][bi] += wv * hs[bi * 1344 + kk];
            }
        }
    }

    for (int o6 = 0; o6 < 6; ++o6)
        for (int bi = 0; bi < 4; ++bi) {
            float v = acc[o6][bi];
            for (int s = 16; s; s >>= 1) v += __shfl_xor_sync(0xffffffffu, v, s);
            if (lane == 0) {
                int o = wid * 6 + o6;
                s1[bi][o] = fmaxf(v + b1[o], 0.f);
            }
        }
    __syncthreads();

    if (tid < 128) {
        int bi = tid >> 5, o = tid & 31;
        float v = b2[o];
        for (int j = 0; j < 48; ++j) v += s1[bi][j] * w2[o * 48 + j];
        s2[bi][o] = fmaxf(v, 0.f);
    }
    __syncthreads();
    if (tid < 64) {
        int bi = tid >> 4, o = tid & 15;
        float v = b3[o];
        for (int j = 0; j < 32; ++j) v += s2[bi][j] * w3[o * 32 + j];
        s3[bi][o] = fmaxf(v, 0.f);
    }
    __syncthreads();
    if (tid < 20) {
        int bi = tid / 5, o = tid % 5;
        float v = b4[o];
        for (int j = 0; j < 16; ++j) v += s3[bi][j] * w4[o * 16 + j];
        g_theta[(b0 + bi) * 5 + o] = tanhf(v);
    }
}

// =====================================================================
// Kernel 5: CPAB integration (double, exact cell-crossing, early-exit)
//           + linear interpolation of the original signal
// =====================================================================
__global__ void __launch_bounds__(256) k_warp(
    const float* __restrict__ x, const float* __restrict__ basis,
    float* __restrict__ out)
{
    __shared__ double As[12];
    const int b = blockIdx.y;
    const int i = blockIdx.x * 256 + threadIdx.x;

    if (threadIdx.x < 12) {
        double s = 0.0;
        for (int d = 0; d < 5; ++d)
            s += (double)g_theta[b * 5 + d] * (double)basis[threadIdx.x * 5 + d];
        As[threadIdx.x] = s;
    }
    __syncthreads();

    float xf = (i == 2047) ? 1.0f : (float)i * (1.0f / 2047.0f);
    double xx = (double)xf;
    double t = 1.0;

    for (int it = 0; it < 7; ++it) {
        if (t == 0.0) break;
        int c = (int)floor(xx * 6.0);
        c = max(0, min(c, 5));
        double a  = As[2 * c];
        double bb = As[2 * c + 1];
        double v = a * xx + bb;
        double xb = (v >= 0.0) ? (double)(c + 1) / 6.0 : (double)c / 6.0;
        bool big_a = fabs(a) > 1e-8;
        double a_s = big_a ? a : 1.0;
        double z  = xx + bb / a_s;
        double zb = xb + bb / a_s;
        double zden = (fabs(z) > 1e-12) ? z : 1e-12;
        double ratio = zb / zden;
        double t_exp = log(fmax(ratio, 1e-12)) / a_s;
        double v_s = (fabs(v) > 1e-12) ? v : 1.0;
        double t_lin = (xb - xx) / v_s;
        double thit = big_a ? t_exp : t_lin;
        bool valid = (fabs(v) > 1e-12) && (thit > 0.0) && ((big_a ? ratio : 1.0) > 0.0);
        if (!valid) thit = 1e300;
        double tau = fmin(t, thit);
        double x_new = big_a ? (z * exp(a * tau) - (z - xx)) : (xx + bb * tau);
        bool hit = (thit <= t);
        double nudge = (v >= 0.0) ? 1e-6 : -1e-6;
        xx = hit ? (xb + nudge) : x_new;
        xx = fmin(fmax(xx, 0.0), 1.0);
        t = fmax(t - tau, 0.0);
    }

    float xt = (float)xx;
    xt = fminf(fmaxf(xt, 0.f), 1.f);
    float p = xt * 2047.0f;
    int x0 = (int)floorf(p);
    x0 = max(0, min(x0, 2046));
    float wgt = p - (float)x0;
    const float* xb_ = x + (size_t)b * 3 * L0;
#pragma unroll
    for (int c = 0; c < 3; ++c) {
        float d0 = xb_[c * L0 + x0];
        float d1 = xb_[c * L0 + x0 + 1];
        out[((size_t)b * 3 + c) * L0 + i] = d0 * (1.f - wgt) + d1 * wgt;
    }
}

// =====================================================================
extern "C" void kernel_launch(void* const* d_in, const int* in_sizes, int n_in,
                              void* d_out, int out_size)
{
    const float* x  = (const float*)d_in[0];

    k_prep<<<40, 256>>>(
        (const float*)d_in[7],  (const float*)d_in[8],  (const float*)d_in[9],
        (const float*)d_in[10], (const float*)d_in[11], (const float*)d_in[12],
        (const float*)d_in[13], (const float*)d_in[14], (const float*)d_in[15],
        (const float*)d_in[16], (const float*)d_in[17], (const float*)d_in[18]);

    k_conv1<<<dim3(16, B), 256>>>(x,
        (const float*)d_in[1], (const float*)d_in[2], (const float*)d_in[3],
        (const float*)d_in[4], (const float*)d_in[5], (const float*)d_in[6]);

    k_conv2m<<<dim3(4, B), 256>>>();

    k_conv3<<<dim3(B, 3), 256>>>();

    k_fc<<<64, 256>>>(
        (const float*)d_in[19], (const float*)d_in[20], (const float*)d_in[21],
        (const float*)d_in[22], (const float*)d_in[23], (const float*)d_in[24],
        (const float*)d_in[25], (const float*)d_in[26]);

    k_warp<<<dim3(8, B), 256>>>(x, (const float*)d_in[27], (float*)d_out);
}